// round 14
// baseline (speedup 1.0000x reference)
#include <cuda_runtime.h>

// ============================================================================
// FINAL KERNEL — at the measured B300 mixed-R/W HBM roofline.
//
// LIF neuron with cache term:
//   mem   = mem/TAU + (1 + ALPHA*cache) * x_t
//   spike = (mem - V_TH > 0); mem = (1-spike)*mem; cache = BETA*cache + (1-spike)
//
// X: [B=32, T=64, N=32768] f32 -> spikes, same shape. Pure streaming,
// 512 MiB compulsory traffic (read once, write once), 1:1 R/W.
//
// Session evidence (R2-R13): eight mechanistically distinct variants —
// register-pipeline depth, L2 prefetch, cp.async SMEM ring, exact
// 14-CTA/SM balance, 256-bit v8 ld/st, dual distant address streams,
// structural 2KB read/write direction-bursts — ALL pin DRAM at 73-76%
// active / ~5.9-6.0 TB/s with kernel time 80.2-83.3 us = 512 MiB /
// achieved BW. Conclusion: ~6 TB/s is the device's effective ceiling
// for a fine-grained 1:1 read/write stream (the 8 TB/s spec is
// unidirectional); no schedule-side knob is binding. This source has
// drawn 90.7 / 92.2 / 90.6 us across three identical-byte runs —
// reproducibly the best configuration.
//
// Numerics: division by TAU=5 via a residual-corrected FMA triple,
// provably bit-identical to __fdiv_rn(x,5) for every float (the true
// quotient lies >= 1/10 ulp from any rounding midpoint while the
// sequence error is ~2^-25 ulp, so the final rounding is exact). All
// other ops use explicit __f*_rn intrinsics to forbid FMA contraction,
// bit-matching the XLA reference — a single threshold flip would
// cascade down the whole T recurrence. rel_err = 0.0 on 12/12 runs.
// ============================================================================

constexpr int B = 32;
constexpr int T = 64;
constexpr int N = 32768;
constexpr int N4 = N / 4;           // 8192 float4 per (b, t) row

__device__ __forceinline__ float div5_exact(float x) {
    const float y = 0.2f;                       // RN(1/5)
    float q = __fmul_rn(x, y);
    float r = __fmaf_rn(q, -5.0f, x);           // exact residual
    return __fmaf_rn(r, y, q);                  // == __fdiv_rn(x, 5.0f)
}

__device__ __forceinline__ float lif_step(float x, float& mem, float& cache) {
    float d = div5_exact(mem);                              // mem / TAU
    float g = __fadd_rn(1.0f, __fmul_rn(0.1f, cache));      // 1 + ALPHA*cache
    mem = __fadd_rn(d, __fmul_rn(g, x));
    bool fired = (mem > 0.5f);                              // mem - V_TH > 0
    float spike = fired ? 1.0f : 0.0f;
    mem = fired ? 0.0f : mem;                               // hard reset to 0
    cache = __fadd_rn(__fmul_rn(0.5f, cache), fired ? 0.0f : 1.0f);
    return spike;
}

__global__ __launch_bounds__(256) void lif_kernel(
    const float4* __restrict__ X, float4* __restrict__ out)
{
    int lane = blockIdx.x * blockDim.x + threadIdx.x;   // [0, B*N4)
    int b = lane >> 13;                                  // lane / N4
    int c = lane & (N4 - 1);                             // lane % N4
    int base = b * (T * N4) + c;

    float4 mem   = make_float4(0.f, 0.f, 0.f, 0.f);
    float4 cache = make_float4(0.f, 0.f, 0.f, 0.f);

    // Prefetch pipeline: x holds the data for step t; the load for
    // step t+1 is issued before the step-t compute body.
    float4 x = __ldcs(&X[base]);

#pragma unroll 8
    for (int t = 0; t < T; ++t) {
        int tn = min(t + 1, T - 1);               // branchless clamp
        float4 xn = __ldcs(&X[base + tn * N4]);   // in flight during compute

        float4 s;
        s.x = lif_step(x.x, mem.x, cache.x);
        s.y = lif_step(x.y, mem.y, cache.y);
        s.z = lif_step(x.z, mem.z, cache.z);
        s.w = lif_step(x.w, mem.w, cache.w);

        __stcs(&out[base + t * N4], s);
        x = xn;
    }
}

extern "C" void kernel_launch(void* const* d_in, const int* in_sizes, int n_in,
                              void* d_out, int out_size) {
    const float4* X = (const float4*)d_in[0];
    float4* out = (float4*)d_out;
    int lanes = B * N4;                 // 262,144
    lif_kernel<<<lanes / 256, 256>>>(X, out);
}

// round 15
// speedup vs baseline: 1.0145x; 1.0145x over previous
#include <cuda_runtime.h>

// LIF neuron with cache term — best-known config (R3 skeleton) with ONE
// isolated change: stores use st.global.wt (write-through) instead of
// __stcs. __stcs still write-allocates dirty lines in L2 whose
// victim-driven writebacks interleave with the X demand-read stream;
// write-through forwards stores toward DRAM without establishing L2
// lines. This is the last unfalsified cache-policy knob (loads/L1/L2
// read policies and all schedule-side knobs were falsified R4-R12,
// all pinning at ~6.0 TB/s / 73-76% DRAM active).
//
//   mem   = mem/TAU + (1 + ALPHA*cache) * x_t
//   spike = (mem - V_TH > 0); mem = (1-spike)*mem; cache = BETA*cache + (1-spike)
//
// Numerics: division by TAU=5 via residual-corrected FMA triple —
// provably bit-identical to __fdiv_rn(x,5) for all floats. All other
// ops use explicit __f*_rn (no FMA contraction) to bit-match the XLA
// reference. rel_err = 0.0 on 13/13 passing runs of this path.

constexpr int B = 32;
constexpr int T = 64;
constexpr int N = 32768;
constexpr int N4 = N / 4;           // 8192 float4 per (b, t) row

__device__ __forceinline__ float div5_exact(float x) {
    const float y = 0.2f;                       // RN(1/5)
    float q = __fmul_rn(x, y);
    float r = __fmaf_rn(q, -5.0f, x);           // exact residual
    return __fmaf_rn(r, y, q);                  // == __fdiv_rn(x, 5.0f)
}

__device__ __forceinline__ float lif_step(float x, float& mem, float& cache) {
    float d = div5_exact(mem);                              // mem / TAU
    float g = __fadd_rn(1.0f, __fmul_rn(0.1f, cache));      // 1 + ALPHA*cache
    mem = __fadd_rn(d, __fmul_rn(g, x));
    bool fired = (mem > 0.5f);                              // mem - V_TH > 0
    float spike = fired ? 1.0f : 0.0f;
    mem = fired ? 0.0f : mem;                               // hard reset to 0
    cache = __fadd_rn(__fmul_rn(0.5f, cache), fired ? 0.0f : 1.0f);
    return spike;
}

__device__ __forceinline__ void stg_wt(float4* p, float4 v) {
    asm volatile("st.global.wt.v4.f32 [%0], {%1,%2,%3,%4};"
                 :: "l"(p), "f"(v.x), "f"(v.y), "f"(v.z), "f"(v.w)
                 : "memory");
}

__global__ __launch_bounds__(256) void lif_kernel(
    const float4* __restrict__ X, float4* __restrict__ out)
{
    int lane = blockIdx.x * blockDim.x + threadIdx.x;   // [0, B*N4)
    int b = lane >> 13;                                  // lane / N4
    int c = lane & (N4 - 1);                             // lane % N4
    int base = b * (T * N4) + c;

    float4 mem   = make_float4(0.f, 0.f, 0.f, 0.f);
    float4 cache = make_float4(0.f, 0.f, 0.f, 0.f);

    // Prefetch pipeline: x holds the data for step t; the load for
    // step t+1 is issued before the step-t compute body.
    float4 x = __ldcs(&X[base]);

#pragma unroll 8
    for (int t = 0; t < T; ++t) {
        int tn = min(t + 1, T - 1);               // branchless clamp
        float4 xn = __ldcs(&X[base + tn * N4]);   // in flight during compute

        float4 s;
        s.x = lif_step(x.x, mem.x, cache.x);
        s.y = lif_step(x.y, mem.y, cache.y);
        s.z = lif_step(x.z, mem.z, cache.z);
        s.w = lif_step(x.w, mem.w, cache.w);

        stg_wt(&out[base + t * N4], s);           // write-through store
        x = xn;
    }
}

extern "C" void kernel_launch(void* const* d_in, const int* in_sizes, int n_in,
                              void* d_out, int out_size) {
    const float4* X = (const float4*)d_in[0];
    float4* out = (float4*)d_out;
    int lanes = B * N4;                 // 262,144
    lif_kernel<<<lanes / 256, 256>>>(X, out);
}